// round 1
// baseline (speedup 1.0000x reference)
#include <cuda_runtime.h>
#include <math.h>

// Problem constants
#define B_ 2
#define CC 512      // concat channels
#define CO 256      // output channels
#define C1 512      // x1 channels
#define HIN 32
#define H_ 64
#define W_ 64
#define HW 4096
#define HWIN 1024
#define OFFC 18
#define K2 9

// Scratch (device globals; no runtime allocation)
__device__ float g_t[B_ * CO * HWIN];      // 1x1-conv'd x1 @ 32x32 (bias NOT added)
__device__ float g_xu[B_ * CO * HW];       // upsampled x1u (with bias) -> concat channels 256..511
__device__ float g_off[B_ * OFFC * HW];    // offset field
__device__ float g_dc[B_ * CO * HW];       // deform conv output (+def_b)
__device__ float g_wT[K2 * CC * CO];       // def_w transposed: [k][ci][co]
__device__ float g_stats[2 * CO];          // mean, rstd per channel

// ---------------------------------------------------------------------------
// K_a: 1x1 conv on x1 at 32x32: g_t[b,co,p] = sum_ci up_w[co,ci]*x1[b,ci,p]
// grid (8 pixel-tiles, 32 co-tiles, 2 batches), 128 threads
__global__ void k_upconv(const float* __restrict__ x1,
                         const float* __restrict__ up_w) {
    __shared__ float ws[8 * 512];
    int b = blockIdx.z;
    int co0 = blockIdx.y * 8;
    int p = blockIdx.x * 128 + threadIdx.x;
    for (int i = threadIdx.x; i < 8 * 512; i += 128) {
        int j = i >> 9, ci = i & 511;
        ws[i] = up_w[(co0 + j) * 512 + ci];
    }
    __syncthreads();
    float acc[8];
#pragma unroll
    for (int j = 0; j < 8; j++) acc[j] = 0.f;
    const float* xp = x1 + b * C1 * HWIN + p;
    for (int ci = 0; ci < 512; ci++) {
        float xv = xp[ci * HWIN];
#pragma unroll
        for (int j = 0; j < 8; j++) acc[j] += ws[j * 512 + ci] * xv;
    }
#pragma unroll
    for (int j = 0; j < 8; j++)
        g_t[(b * CO + co0 + j) * HWIN + p] = acc[j];
}

// ---------------------------------------------------------------------------
// K_b: bilinear upsample 32->64 (align_corners) of g_t, add up_b
__global__ void k_upsample(const float* __restrict__ up_b) {
    int idx = blockIdx.x * 256 + threadIdx.x;
    if (idx >= B_ * CO * HW) return;
    int p = idx & (HW - 1);
    int c = (idx >> 12) & (CO - 1);
    int h = p >> 6, w = p & 63;
    const float scale = 31.0f / 63.0f;
    float fh = h * scale;
    int i0 = (int)floorf(fh); if (i0 > 30) i0 = 30;
    float wy = fh - (float)i0;
    float fw = w * scale;
    int j0 = (int)floorf(fw); if (j0 > 30) j0 = 30;
    float wx = fw - (float)j0;
    const float* t = g_t + (idx >> 12) * HWIN;  // (b*CO+c)*1024
    float v00 = t[i0 * 32 + j0];
    float v01 = t[i0 * 32 + j0 + 1];
    float v10 = t[(i0 + 1) * 32 + j0];
    float v11 = t[(i0 + 1) * 32 + j0 + 1];
    float v = (1.f - wy) * ((1.f - wx) * v00 + wx * v01) +
              wy * ((1.f - wx) * v10 + wx * v11);
    g_xu[idx] = v + up_b[c];
}

// ---------------------------------------------------------------------------
// K_off: 3x3 conv pad=1 on concat x (x2 ++ g_xu), 512 -> 18
// grid (H, B), 64 threads (one per w)
__global__ void k_offconv(const float* __restrict__ x2,
                          const float* __restrict__ off_w,
                          const float* __restrict__ off_b) {
    __shared__ float xr[3][66];
    __shared__ float ws[162];
    int b = blockIdx.y, h = blockIdx.x, t = threadIdx.x;
    float acc[18];
#pragma unroll
    for (int c = 0; c < 18; c++) acc[c] = 0.f;
    for (int ci = 0; ci < 512; ci++) {
        const float* plane = (ci < 256)
            ? x2 + (b * 256 + ci) * HW
            : g_xu + (b * 256 + (ci - 256)) * HW;
        for (int s = t; s < 198; s += 64) {
            int r = s / 66, cc = s % 66 - 1;
            int y = h - 1 + r;
            xr[r][s % 66] = (y >= 0 && y < 64 && cc >= 0 && cc < 64)
                                ? plane[y * 64 + cc] : 0.f;
        }
        for (int s = t; s < 162; s += 64)
            ws[s] = off_w[((s / 9) * 512 + ci) * 9 + (s % 9)];
        __syncthreads();
#pragma unroll
        for (int tap = 0; tap < 9; tap++) {
            float xv = xr[tap / 3][t + tap % 3];
#pragma unroll
            for (int c = 0; c < 18; c++) acc[c] += ws[c * 9 + tap] * xv;
        }
        __syncthreads();
    }
#pragma unroll
    for (int c = 0; c < 18; c++)
        g_off[(b * OFFC + c) * HW + h * 64 + t] = acc[c] + off_b[c];
}

// ---------------------------------------------------------------------------
// K_wT: transpose def_w (co,ci,k) -> (k,ci,co); write-coalesced
__global__ void k_wt(const float* __restrict__ def_w) {
    int i = blockIdx.x * 256 + threadIdx.x;
    if (i >= K2 * CC * CO) return;
    int co = i & 255;
    int ci = (i >> 8) & 511;
    int k = i >> 17;
    g_wT[i] = def_w[(co * 512 + ci) * 9 + k];
}

// ---------------------------------------------------------------------------
// K_def: deformable conv. Block = (b, 16-pixel tile); 128 threads,
// each thread owns co = 2t, 2t+1 and 16-pixel accumulators.
#define PIX 16
#define CICHUNK 64
__global__ void __launch_bounds__(128) k_deform(const float* __restrict__ x2,
                                                const float* __restrict__ def_b) {
    __shared__ float v_sh[CICHUNK][PIX];
    __shared__ float cwt[4][PIX];
    __shared__ int ciy[PIX], cix[PIX];
    int b = blockIdx.y;
    int p0 = blockIdx.x * PIX;
    int t = threadIdx.x;
    float acc0[PIX], acc1[PIX];
#pragma unroll
    for (int i = 0; i < PIX; i++) { acc0[i] = 0.f; acc1[i] = 0.f; }
    const float* offp = g_off + b * OFFC * HW;

    for (int k = 0; k < 9; k++) {
        __syncthreads();
        if (t < PIX) {
            int p = p0 + t;
            int h = p >> 6, w = p & 63;
            float dy = offp[(2 * k) * HW + p];
            float dx = offp[(2 * k + 1) * HW + p];
            float py = (float)h + (float)(k / 3) - 1.f + dy;
            float px = (float)w + (float)(k % 3) - 1.f + dx;
            float fy = floorf(py), fx = floorf(px);
            float wy = py - fy, wx = px - fx;
            ciy[t] = (int)fy;
            cix[t] = (int)fx;
            cwt[0][t] = (1.f - wy) * (1.f - wx);
            cwt[1][t] = (1.f - wy) * wx;
            cwt[2][t] = wy * (1.f - wx);
            cwt[3][t] = wy * wx;
        }
        __syncthreads();
        for (int c0 = 0; c0 < CC; c0 += CICHUNK) {
            // cooperative fill: 64 ci x 16 pix = 1024 entries / 128 threads
#pragma unroll
            for (int j = 0; j < (CICHUNK * PIX) / 128; j++) {
                int e = t + j * 128;
                int pi = e & (PIX - 1);
                int cl = e >> 4;
                int ci = c0 + cl;
                const float* plane = (ci < 256)
                    ? x2 + (b * 256 + ci) * HW
                    : g_xu + (b * 256 + (ci - 256)) * HW;
                int y0 = ciy[pi], x0 = cix[pi];
                float v = 0.f;
                if ((unsigned)y0 < 64u) {
                    const float* r = plane + y0 * 64;
                    if ((unsigned)x0 < 64u) v += cwt[0][pi] * r[x0];
                    if ((unsigned)(x0 + 1) < 64u) v += cwt[1][pi] * r[x0 + 1];
                }
                if ((unsigned)(y0 + 1) < 64u) {
                    const float* r = plane + (y0 + 1) * 64;
                    if ((unsigned)x0 < 64u) v += cwt[2][pi] * r[x0];
                    if ((unsigned)(x0 + 1) < 64u) v += cwt[3][pi] * r[x0 + 1];
                }
                v_sh[cl][pi] = v;
            }
            __syncthreads();
            const float2* wp =
                (const float2*)(g_wT + (k * CC + c0) * CO) + t;  // co = 2t, 2t+1
            for (int cl = 0; cl < CICHUNK; cl++) {
                float2 wv = wp[cl * 128];
                const float4* vv = (const float4*)v_sh[cl];
#pragma unroll
                for (int q = 0; q < PIX / 4; q++) {
                    float4 vq = vv[q];
                    acc0[4 * q + 0] += wv.x * vq.x;
                    acc0[4 * q + 1] += wv.x * vq.y;
                    acc0[4 * q + 2] += wv.x * vq.z;
                    acc0[4 * q + 3] += wv.x * vq.w;
                    acc1[4 * q + 0] += wv.y * vq.x;
                    acc1[4 * q + 1] += wv.y * vq.y;
                    acc1[4 * q + 2] += wv.y * vq.z;
                    acc1[4 * q + 3] += wv.y * vq.w;
                }
            }
            __syncthreads();
        }
    }
    int co0 = 2 * t, co1 = 2 * t + 1;
    float bb0 = def_b[co0], bb1 = def_b[co1];
    float* o0 = g_dc + (b * CO + co0) * HW + p0;
    float* o1 = g_dc + (b * CO + co1) * HW + p0;
#pragma unroll
    for (int q = 0; q < PIX / 4; q++) {
        float4 s0 = make_float4(acc0[4*q] + bb0, acc0[4*q+1] + bb0,
                                acc0[4*q+2] + bb0, acc0[4*q+3] + bb0);
        float4 s1 = make_float4(acc1[4*q] + bb1, acc1[4*q+1] + bb1,
                                acc1[4*q+2] + bb1, acc1[4*q+3] + bb1);
        ((float4*)o0)[q] = s0;
        ((float4*)o1)[q] = s1;
    }
}

// ---------------------------------------------------------------------------
// K_stats: per-channel mean/rstd over (B,H,W) — deterministic tree reduction
__global__ void k_stats() {
    int co = blockIdx.x, t = threadIdx.x;
    const float* p0 = g_dc + co * HW;
    const float* p1 = g_dc + (CO + co) * HW;
    float s = 0.f, s2 = 0.f;
    for (int i = t; i < HW; i += 256) {
        float v = p0[i]; s += v; s2 += v * v;
        v = p1[i]; s += v; s2 += v * v;
    }
    __shared__ float sh[256], sh2[256];
    sh[t] = s; sh2[t] = s2;
    __syncthreads();
    for (int o = 128; o > 0; o >>= 1) {
        if (t < o) { sh[t] += sh[t + o]; sh2[t] += sh2[t + o]; }
        __syncthreads();
    }
    if (t == 0) {
        float m = sh[0] * (1.f / 8192.f);
        float var = sh2[0] * (1.f / 8192.f) - m * m;
        g_stats[co] = m;
        g_stats[CO + co] = rsqrtf(var + 1e-5f);
    }
}

// ---------------------------------------------------------------------------
// K_final: shortcut 1x1 conv + BN apply + relu
__global__ void k_final(const float* __restrict__ x2,
                        const float* __restrict__ sc_w,
                        const float* __restrict__ sc_b,
                        const float* __restrict__ gamma,
                        const float* __restrict__ beta,
                        float* __restrict__ out) {
    __shared__ float ws[8 * 512];
    int b = blockIdx.z;
    int co0 = blockIdx.y * 8;
    int p = blockIdx.x * 128 + threadIdx.x;
    for (int i = threadIdx.x; i < 8 * 512; i += 128) {
        int j = i >> 9, ci = i & 511;
        ws[i] = sc_w[(co0 + j) * 512 + ci];
    }
    __syncthreads();
    float acc[8];
#pragma unroll
    for (int j = 0; j < 8; j++) acc[j] = 0.f;
    const float* xp = x2 + b * 256 * HW + p;
    for (int ci = 0; ci < 256; ci++) {
        float xv = xp[ci * HW];
#pragma unroll
        for (int j = 0; j < 8; j++) acc[j] += ws[j * 512 + ci] * xv;
    }
    const float* up = g_xu + b * 256 * HW + p;
    for (int ci = 0; ci < 256; ci++) {
        float xv = up[ci * HW];
#pragma unroll
        for (int j = 0; j < 8; j++) acc[j] += ws[j * 512 + 256 + ci] * xv;
    }
#pragma unroll
    for (int j = 0; j < 8; j++) {
        int co = co0 + j;
        float m = g_stats[co], r = g_stats[CO + co];
        float v = (g_dc[(b * CO + co) * HW + p] - m) * r * gamma[co] +
                  beta[co] + acc[j] + sc_b[co];
        out[(b * CO + co) * HW + p] = fmaxf(v, 0.f);
    }
}

// ---------------------------------------------------------------------------
extern "C" void kernel_launch(void* const* d_in, const int* in_sizes, int n_in,
                              void* d_out, int out_size) {
    const float* x1    = (const float*)d_in[0];
    const float* x2    = (const float*)d_in[1];
    const float* up_w  = (const float*)d_in[2];
    const float* up_b  = (const float*)d_in[3];
    const float* off_w = (const float*)d_in[4];
    const float* off_b = (const float*)d_in[5];
    const float* def_w = (const float*)d_in[6];
    const float* def_b = (const float*)d_in[7];
    const float* bn_g  = (const float*)d_in[8];
    const float* bn_b  = (const float*)d_in[9];
    const float* sc_w  = (const float*)d_in[10];
    const float* sc_b  = (const float*)d_in[11];
    float* out = (float*)d_out;

    // 1x1 conv at low res, then upsample
    k_upconv<<<dim3(HWIN / 128, CO / 8, B_), 128>>>(x1, up_w);
    k_upsample<<<(B_ * CO * HW + 255) / 256, 256>>>(up_b);

    // weight transpose for deform GEMMs
    k_wt<<<(K2 * CC * CO + 255) / 256, 256>>>(def_w);

    // offset field
    k_offconv<<<dim3(H_, B_), 64>>>(x2, off_w, off_b);

    // deformable conv
    k_deform<<<dim3(HW / PIX, B_), 128>>>(x2, def_b);

    // BN stats
    k_stats<<<CO, 256>>>();

    // shortcut conv + BN + relu
    k_final<<<dim3(HW / 128, CO / 8, B_), 128>>>(x2, sc_w, sc_b, bn_g, bn_b, out);
}

// round 2
// speedup vs baseline: 1.9200x; 1.9200x over previous
#include <cuda_runtime.h>
#include <math.h>

// Problem constants
#define B_ 2
#define CC 512      // concat channels
#define CO 256      // output channels
#define C1 512      // x1 channels
#define H_ 64
#define W_ 64
#define HW 4096
#define HWIN 1024
#define OFFC 18
#define K2 9

typedef unsigned long long ull;

// Packed f32x2 helpers (Blackwell FFMA2 path)
__device__ __forceinline__ ull pack2(float lo, float hi) {
    ull r; asm("mov.b64 %0, {%1,%2};" : "=l"(r) : "f"(lo), "f"(hi)); return r;
}
__device__ __forceinline__ void fma2(ull& d, ull a, ull b) {
    asm("fma.rn.f32x2 %0, %1, %2, %0;" : "+l"(d) : "l"(a), "l"(b));
}
__device__ __forceinline__ float2 unpack2(ull v) {
    float2 r; asm("mov.b64 {%0,%1}, %2;" : "=f"(r.x), "=f"(r.y) : "l"(v)); return r;
}

// Scratch (device globals; no runtime allocation)
__device__ float g_t[B_ * CO * HWIN];          // 1x1-conv'd x1 @ 32x32 (no bias)
__device__ __align__(16) float g_x[B_ * CC * HW];  // concat tensor [b][512][64][64]
__device__ float g_off[B_ * OFFC * HW];        // final offset field
__device__ float g_offp[B_ * 4 * OFFC * HW];   // offset partials (4 ci-chunks)
__device__ float g_dc[B_ * CO * HW];           // deform conv output (+def_b)
__device__ __align__(16) float g_wT[K2 * CC * CO + 256];  // def_w [k][ci][co] (+pad)
__device__ float g_stats[2 * CO];              // mean, rstd per channel

// ---------------------------------------------------------------------------
// 1x1 conv on x1 at 32x32 (transposed weight staging + FFMA2)
__global__ void k_upconv(const float* __restrict__ x1,
                         const float* __restrict__ up_w) {
    __shared__ __align__(16) float ws[8 * 512];   // [ci][j]
    int b = blockIdx.z;
    int co0 = blockIdx.y * 8;
    int p = blockIdx.x * 128 + threadIdx.x;
    for (int i = threadIdx.x; i < 4096; i += 128) {
        int j = i >> 9, ci = i & 511;
        ws[ci * 8 + j] = up_w[(co0 + j) * 512 + ci];
    }
    __syncthreads();
    ull a[4] = {0ull, 0ull, 0ull, 0ull};
    const float* xp = x1 + b * C1 * HWIN + p;
#pragma unroll 4
    for (int ci = 0; ci < 512; ci++) {
        float xv = __ldg(xp + ci * HWIN);
        ull xv2 = pack2(xv, xv);
        const ull* wr = (const ull*)(ws + ci * 8);
        fma2(a[0], wr[0], xv2);
        fma2(a[1], wr[1], xv2);
        fma2(a[2], wr[2], xv2);
        fma2(a[3], wr[3], xv2);
    }
#pragma unroll
    for (int jp = 0; jp < 4; jp++) {
        float2 u = unpack2(a[jp]);
        g_t[(b * CO + co0 + 2 * jp) * HWIN + p] = u.x;
        g_t[(b * CO + co0 + 2 * jp + 1) * HWIN + p] = u.y;
    }
}

// ---------------------------------------------------------------------------
// Copy x2 into concat buffer channels [0,256)
__global__ void k_copy(const float* __restrict__ x2) {
    int i = blockIdx.x * 256 + threadIdx.x;       // float4 index, n = 2^19
    if (i >= B_ * 256 * (HW / 4)) return;
    int b = i >> 18;
    int c = (i >> 10) & 255;
    int p4 = i & 1023;
    ((float4*)g_x)[((b * 512) + c) * 1024 + p4] =
        ((const float4*)x2)[i];
}

// ---------------------------------------------------------------------------
// Bilinear upsample 32->64 (align_corners) of g_t, add up_b, write into
// concat buffer channels [256,512)
__global__ void k_upsample(const float* __restrict__ up_b) {
    int idx = blockIdx.x * 256 + threadIdx.x;
    if (idx >= B_ * CO * HW) return;
    int p = idx & (HW - 1);
    int c = (idx >> 12) & (CO - 1);
    int b = idx >> 20;
    int h = p >> 6, w = p & 63;
    const float scale = 31.0f / 63.0f;
    float fh = h * scale;
    int i0 = (int)floorf(fh); if (i0 > 30) i0 = 30;
    float wy = fh - (float)i0;
    float fw = w * scale;
    int j0 = (int)floorf(fw); if (j0 > 30) j0 = 30;
    float wx = fw - (float)j0;
    const float* t = g_t + (idx >> 12) * HWIN;
    float v00 = t[i0 * 32 + j0];
    float v01 = t[i0 * 32 + j0 + 1];
    float v10 = t[(i0 + 1) * 32 + j0];
    float v11 = t[(i0 + 1) * 32 + j0 + 1];
    float v = (1.f - wy) * ((1.f - wx) * v00 + wx * v01) +
              wy * ((1.f - wx) * v10 + wx * v11);
    g_x[((b * 512) + 256 + c) * HW + p] = v + up_b[c];
}

// ---------------------------------------------------------------------------
// Offset conv partials: 3x3 pad=1, 512->18, ci split into 4 chunks of 128.
// grid (64 rows, 4 chunks, 2 batch), 64 threads (one per w).
__global__ void k_offconv(const float* __restrict__ off_w) {
    __shared__ __align__(16) float xr[8][3][66];
    __shared__ __align__(16) float wsh[8][9 * 18];  // [ciL][tap*18 + c]
    int b = blockIdx.z, cc = blockIdx.y, h = blockIdx.x, t = threadIdx.x;
    int ci0 = cc * 128;
    ull a[9];
#pragma unroll
    for (int c = 0; c < 9; c++) a[c] = 0ull;
    for (int s8 = 0; s8 < 128; s8 += 8) {
        // stage input rows for 8 ci
        for (int idx = t; idx < 8 * 198; idx += 64) {
            int ciL = idx / 198;
            int rem = idx - ciL * 198;
            int r = rem / 66;
            int c66 = rem - r * 66;
            int cw = c66 - 1;
            int y = h - 1 + r;
            const float* pl = g_x + ((b * 512 + ci0 + s8 + ciL) << 12);
            xr[ciL][r][c66] = (y >= 0 && y < 64 && cw >= 0 && cw < 64)
                                  ? pl[y * 64 + cw] : 0.f;
        }
        // stage transposed weights for 8 ci
        for (int idx = t; idx < 8 * 162; idx += 64) {
            int ciL = idx / 162;
            int rem = idx - ciL * 162;
            int tap = rem / 18;
            int c = rem - tap * 18;
            int ci = ci0 + s8 + ciL;
            wsh[ciL][rem] = off_w[(c * 512 + ci) * 9 + tap];
        }
        __syncthreads();
#pragma unroll 2
        for (int ciL = 0; ciL < 8; ciL++) {
#pragma unroll
            for (int tap = 0; tap < 9; tap++) {
                float xv = xr[ciL][tap / 3][t + tap % 3];
                ull xv2 = pack2(xv, xv);
                const ull* wr = (const ull*)&wsh[ciL][tap * 18];
#pragma unroll
                for (int c2 = 0; c2 < 9; c2++) fma2(a[c2], wr[c2], xv2);
            }
        }
        __syncthreads();
    }
#pragma unroll
    for (int c2 = 0; c2 < 9; c2++) {
        float2 u = unpack2(a[c2]);
        float* dst = g_offp + ((b * 4 + cc) * OFFC) * HW + h * 64 + t;
        dst[(2 * c2) * HW] = u.x;
        dst[(2 * c2 + 1) * HW] = u.y;
    }
}

// Reduce 4 ci-chunk partials + bias
__global__ void k_offred(const float* __restrict__ off_b) {
    int idx = blockIdx.x * 256 + threadIdx.x;
    if (idx >= B_ * OFFC * HW) return;
    int b = idx / (OFFC * HW);
    int rem = idx - b * OFFC * HW;
    int c = rem >> 12;
    float s = off_b[c];
#pragma unroll
    for (int cc = 0; cc < 4; cc++)
        s += g_offp[(b * 4 + cc) * OFFC * HW + rem];
    g_off[idx] = s;
}

// ---------------------------------------------------------------------------
// Transpose def_w (co,ci,k) -> (k,ci,co)
__global__ void k_wt(const float* __restrict__ def_w) {
    int i = blockIdx.x * 256 + threadIdx.x;
    if (i >= K2 * CC * CO) return;
    int co = i & 255;
    int ci = (i >> 8) & 511;
    int k = i >> 17;
    g_wT[i] = def_w[(co * 512 + ci) * 9 + k];
}

// ---------------------------------------------------------------------------
// Deformable conv. Block = (16-pixel tile, batch); 128 threads,
// thread t owns co = 2t, 2t+1; FFMA2 over pixel pairs.
#define PIX 16
#define CICHUNK 64
__global__ void __launch_bounds__(128) k_deform(const float* __restrict__ def_b) {
    __shared__ __align__(16) float v_sh[CICHUNK][PIX];
    __shared__ int4 offs[PIX];
    __shared__ float4 cws[PIX];
    int b = blockIdx.y;
    int p0 = blockIdx.x * PIX;
    int t = threadIdx.x;
    ull accA[8], accB[8];
#pragma unroll
    for (int q = 0; q < 8; q++) { accA[q] = 0ull; accB[q] = 0ull; }
    const float* offp = g_off + b * OFFC * HW;
    const float* xb = g_x + (b * 512) * HW;

    for (int k = 0; k < 9; k++) {
        if (t < PIX) {
            int p = p0 + t;
            int h = p >> 6, w = p & 63;
            float dy = offp[(2 * k) * HW + p];
            float dx = offp[(2 * k + 1) * HW + p];
            float py = (float)h + (float)(k / 3) - 1.f + dy;
            float px = (float)w + (float)(k % 3) - 1.f + dx;
            float fy = floorf(py), fx = floorf(px);
            float wy = py - fy, wx = px - fx;
            int y0 = (int)fy, x0 = (int)fx;
            int y1 = y0 + 1, x1 = x0 + 1;
            bool vy0 = (unsigned)y0 < 64u, vy1 = (unsigned)y1 < 64u;
            bool vx0 = (unsigned)x0 < 64u, vx1 = (unsigned)x1 < 64u;
            int y0c = min(max(y0, 0), 63), y1c = min(max(y1, 0), 63);
            int x0c = min(max(x0, 0), 63), x1c = min(max(x1, 0), 63);
            cws[t] = make_float4((vy0 && vx0) ? (1.f - wy) * (1.f - wx) : 0.f,
                                 (vy0 && vx1) ? (1.f - wy) * wx : 0.f,
                                 (vy1 && vx0) ? wy * (1.f - wx) : 0.f,
                                 (vy1 && vx1) ? wy * wx : 0.f);
            offs[t] = make_int4(y0c * 64 + x0c, y0c * 64 + x1c,
                                y1c * 64 + x0c, y1c * 64 + x1c);
        }
        __syncthreads();
        for (int c0 = 0; c0 < CC; c0 += CICHUNK) {
            const float* base = xb + c0 * HW;
#pragma unroll
            for (int j = 0; j < (CICHUNK * PIX) / 128; j++) {
                int e = t + j * 128;
                int pi = e & (PIX - 1);
                int cl = e >> 4;
                int4 o = offs[pi];
                float4 cw = cws[pi];
                const float* pl = base + (cl << 12);
                v_sh[cl][pi] = cw.x * __ldg(pl + o.x) + cw.y * __ldg(pl + o.y) +
                               cw.z * __ldg(pl + o.z) + cw.w * __ldg(pl + o.w);
            }
            __syncthreads();
            const float2* wp = (const float2*)(g_wT + (k * CC + c0) * CO) + t;
            float2 wv = wp[0];
            for (int cl = 0; cl < CICHUNK; cl++) {
                float2 wn = wp[(cl + 1) * 128];   // g_wT padded; safe prefetch
                ull wx2 = pack2(wv.x, wv.x);
                ull wy2 = pack2(wv.y, wv.y);
                const ull* vv = (const ull*)v_sh[cl];
#pragma unroll
                for (int q = 0; q < 8; q++) {
                    ull bq = vv[q];
                    fma2(accA[q], wx2, bq);
                    fma2(accB[q], wy2, bq);
                }
                wv = wn;
            }
            __syncthreads();
        }
    }
    int co0 = 2 * t, co1 = 2 * t + 1;
    float bb0 = def_b[co0], bb1 = def_b[co1];
    float* o0 = g_dc + (b * CO + co0) * HW + p0;
    float* o1 = g_dc + (b * CO + co1) * HW + p0;
#pragma unroll
    for (int q = 0; q < 8; q++) {
        float2 u0 = unpack2(accA[q]);
        float2 u1 = unpack2(accB[q]);
        ((float2*)o0)[q] = make_float2(u0.x + bb0, u0.y + bb0);
        ((float2*)o1)[q] = make_float2(u1.x + bb1, u1.y + bb1);
    }
}

// ---------------------------------------------------------------------------
// BN stats: per-channel mean/rstd (deterministic tree reduction)
__global__ void k_stats() {
    int co = blockIdx.x, t = threadIdx.x;
    const float* p0 = g_dc + co * HW;
    const float* p1 = g_dc + (CO + co) * HW;
    float s = 0.f, s2 = 0.f;
    for (int i = t; i < HW; i += 256) {
        float v = p0[i]; s += v; s2 += v * v;
        v = p1[i]; s += v; s2 += v * v;
    }
    __shared__ float sh[256], sh2[256];
    sh[t] = s; sh2[t] = s2;
    __syncthreads();
    for (int o = 128; o > 0; o >>= 1) {
        if (t < o) { sh[t] += sh[t + o]; sh2[t] += sh2[t + o]; }
        __syncthreads();
    }
    if (t == 0) {
        float m = sh[0] * (1.f / 8192.f);
        float var = sh2[0] * (1.f / 8192.f) - m * m;
        g_stats[co] = m;
        g_stats[CO + co] = rsqrtf(var + 1e-5f);
    }
}

// ---------------------------------------------------------------------------
// Shortcut 1x1 conv (on concat buffer) + BN apply + relu
__global__ void k_final(const float* __restrict__ sc_w,
                        const float* __restrict__ sc_b,
                        const float* __restrict__ gamma,
                        const float* __restrict__ beta,
                        float* __restrict__ out) {
    __shared__ __align__(16) float ws[8 * 512];   // [ci][j]
    int b = blockIdx.z;
    int co0 = blockIdx.y * 8;
    int p = blockIdx.x * 128 + threadIdx.x;
    for (int i = threadIdx.x; i < 4096; i += 128) {
        int j = i >> 9, ci = i & 511;
        ws[ci * 8 + j] = sc_w[(co0 + j) * 512 + ci];
    }
    __syncthreads();
    ull a[4] = {0ull, 0ull, 0ull, 0ull};
    const float* xp = g_x + b * 512 * HW + p;
#pragma unroll 4
    for (int ci = 0; ci < 512; ci++) {
        float xv = __ldg(xp + ci * HW);
        ull xv2 = pack2(xv, xv);
        const ull* wr = (const ull*)(ws + ci * 8);
        fma2(a[0], wr[0], xv2);
        fma2(a[1], wr[1], xv2);
        fma2(a[2], wr[2], xv2);
        fma2(a[3], wr[3], xv2);
    }
#pragma unroll
    for (int jp = 0; jp < 4; jp++) {
        float2 u = unpack2(a[jp]);
#pragma unroll
        for (int half = 0; half < 2; half++) {
            int co = co0 + 2 * jp + half;
            float accv = half ? u.y : u.x;
            float m = g_stats[co], r = g_stats[CO + co];
            float v = (g_dc[(b * CO + co) * HW + p] - m) * r * gamma[co] +
                      beta[co] + accv + sc_b[co];
            out[(b * CO + co) * HW + p] = fmaxf(v, 0.f);
        }
    }
}

// ---------------------------------------------------------------------------
extern "C" void kernel_launch(void* const* d_in, const int* in_sizes, int n_in,
                              void* d_out, int out_size) {
    const float* x1    = (const float*)d_in[0];
    const float* x2    = (const float*)d_in[1];
    const float* up_w  = (const float*)d_in[2];
    const float* up_b  = (const float*)d_in[3];
    const float* off_w = (const float*)d_in[4];
    const float* off_b = (const float*)d_in[5];
    const float* def_w = (const float*)d_in[6];
    const float* def_b = (const float*)d_in[7];
    const float* bn_g  = (const float*)d_in[8];
    const float* bn_b  = (const float*)d_in[9];
    const float* sc_w  = (const float*)d_in[10];
    const float* sc_b  = (const float*)d_in[11];
    float* out = (float*)d_out;

    k_upconv<<<dim3(HWIN / 128, CO / 8, B_), 128>>>(x1, up_w);
    k_copy<<<(B_ * 256 * (HW / 4) + 255) / 256, 256>>>(x2);
    k_upsample<<<(B_ * CO * HW + 255) / 256, 256>>>(up_b);
    k_wt<<<(K2 * CC * CO + 255) / 256, 256>>>(def_w);
    k_offconv<<<dim3(H_, 4, B_), 64>>>(off_w);
    k_offred<<<(B_ * OFFC * HW + 255) / 256, 256>>>(off_b);
    k_deform<<<dim3(HW / PIX, B_), 128>>>(def_b);
    k_stats<<<CO, 256>>>();
    k_final<<<dim3(HW / 128, CO / 8, B_), 128>>>(sc_w, sc_b, bn_g, bn_b, out);
}